// round 16
// baseline (speedup 1.0000x reference)
#include <cuda_runtime.h>
#include <cuda_fp16.h>
#include <mma.h>
#include <cstdint>

using namespace nvcuda;

// ---------------------------------------------------------------------------
// Problem constants
// ---------------------------------------------------------------------------
#define NB      2
#define LQ      19560
#define DMODEL  256
#define NHEADS  8
#define NLEV    4
#define NPTS    4
#define HDIM    32
#define NROWS   (NB * LQ)   // 39120
#define KSTRIDE 256

// FPN level shapes (fixed by the problem definition)
__device__ __constant__ const int LVL_H[4] = {92, 46, 23, 12};
__device__ __constant__ const int LVL_W[4] = {160, 80, 40, 20};
__device__ __constant__ const int LVL_S[4] = {0, 14720, 18400, 19320};

// ---------------------------------------------------------------------------
// Device scratch (static; no cudaMalloc allowed)
// ---------------------------------------------------------------------------
__device__ __align__(256) __half g_value0[NROWS * DMODEL];
__device__ __align__(256) __half g_value1[NROWS * DMODEL];
__device__ __align__(256) float  g_off0[NROWS * DMODEL];
__device__ __align__(256) float  g_off1[NROWS * DMODEL];
__device__ __align__(256) float  g_aw0[NROWS * 128];
__device__ __align__(256) float  g_aw1[NROWS * 128];
__device__ __align__(256) float  g_d0[NROWS * DMODEL];
__device__ __align__(256) float  g_d1[NROWS * DMODEL];
__device__ __align__(256) __half g_Whv[DMODEL * DMODEL];     // half, K-major
__device__ __align__(256) __half g_Whso[DMODEL * DMODEL];
__device__ __align__(256) __half g_Whaw[128 * DMODEL];
__device__ __align__(256) __half g_Whf0[DMODEL * DMODEL];    // (W_o@W_aggT)^T half
__device__ __align__(256) __half g_Whf1[DMODEL * DMODEL];
__device__ __align__(256) float  g_bf[DMODEL];

// ---------------------------------------------------------------------------
// Batched transpose fp32 -> half, K-major. blockIdx.z selects matrix.
// ---------------------------------------------------------------------------
__global__ void transpose_batch_kernel(
    const float* __restrict__ W_v, const float* __restrict__ W_so,
    const float* __restrict__ W_aw,
    __half* __restrict__ Whv, __half* __restrict__ Whso, __half* __restrict__ Whaw)
{
    const float* in; __half* out; int C;
    if (blockIdx.z == 0)      { in = W_v;  out = Whv;  C = 256; }
    else if (blockIdx.z == 1) { in = W_so; out = Whso; C = 256; }
    else                      { in = W_aw; out = Whaw; C = 128; }
    const int R = 256;

    __shared__ float t[32][33];
    int bx = blockIdx.x * 32, by = blockIdx.y * 32;
    int x = bx + threadIdx.x;
#pragma unroll
    for (int i = 0; i < 32; i += 8) {
        int y = by + threadIdx.y + i;
        if (x < C && y < R) t[threadIdx.y + i][threadIdx.x] = in[(size_t)y * C + x];
    }
    __syncthreads();
    int x2 = by + threadIdx.x;
#pragma unroll
    for (int i = 0; i < 32; i += 8) {
        int y2 = bx + threadIdx.y + i;
        if (x2 < R && y2 < C) out[(size_t)y2 * R + x2] = __float2half(t[threadIdx.x][threadIdx.y + i]);
    }
}

// ---------------------------------------------------------------------------
// wfprep: Whf_i[j][m] = half( sum_k W_o[m][k] * W_agg_i[k][j] )
// ---------------------------------------------------------------------------
__global__ __launch_bounds__(256) void wfprep_kernel(
    const float* __restrict__ W_o, const float* __restrict__ W_agg,
    __half* __restrict__ Whf0, __half* __restrict__ Whf1)
{
    __shared__ float sA[16][256];
    const float* Wagg = W_agg + (size_t)blockIdx.y * 256 * 256;
    __half* Whf = blockIdx.y ? Whf1 : Whf0;
    const int m0 = blockIdx.x * 16;
    const int tid = threadIdx.x;

    for (int i = tid; i < 16 * 256; i += 256)
        sA[i >> 8][i & 255] = W_o[(size_t)(m0 + (i >> 8)) * 256 + (i & 255)];
    __syncthreads();

    const int j = tid;
    float acc[16];
#pragma unroll
    for (int m = 0; m < 16; m++) acc[m] = 0.f;
    for (int k = 0; k < 256; k++) {
        float b = Wagg[(size_t)k * 256 + j];
#pragma unroll
        for (int m = 0; m < 16; m++) acc[m] = fmaf(sA[m][k], b, acc[m]);
    }
#pragma unroll
    for (int m = 0; m < 16; m++)
        Whf[(size_t)j * 256 + m0 + m] = __float2half(acc[m]);
}

// ---------------------------------------------------------------------------
// bf[j] = b_agg[j] + sum_m b_o[m] * (W_agg[m][j] + W_agg[m+256][j])
// ---------------------------------------------------------------------------
__global__ void fuse_bias_kernel(const float* __restrict__ b_o,
                                 const float* __restrict__ b_agg,
                                 const float* __restrict__ W_agg,
                                 float* __restrict__ bf)
{
    int j = threadIdx.x;
    float s = b_agg[j];
    for (int m = 0; m < DMODEL; m++)
        s += b_o[m] * (W_agg[(size_t)m * DMODEL + j] +
                       W_agg[(size_t)(m + DMODEL) * DMODEL + j]);
    bf[j] = s;
}

// ---------------------------------------------------------------------------
// fp16 wmma GEMM (m16n16k16, fp32 accum).  (R7/R10/R12/R14-proven)
// ---------------------------------------------------------------------------
template <int NT, int EPI>
__global__ __launch_bounds__(256) void gemm_hmma(
    const float* __restrict__ A0, const float* __restrict__ A1, int chunksA,
    const __half* __restrict__ B0, const __half* __restrict__ B1, int chunksTot,
    const float* __restrict__ bias, void* __restrict__ Cout, int M)
{
    __shared__ __align__(128) union {
        struct { __half A[128][72]; __half B[64][72]; } ld;  // 27648 B
        float C[128][72];                                    // 36864 B
    } sm;

    const int tid = threadIdx.x;
    const int wid = tid >> 5;
    const int wm = (wid & 3) * 32;
    const int wn = (wid >> 2) * 32;
    const int mbase = blockIdx.y * 128;
    const int ncol0 = blockIdx.x * 64;

    wmma::fragment<wmma::accumulator, 16, 16, 16, float> acc[2][2];
#pragma unroll
    for (int i = 0; i < 2; i++)
#pragma unroll
        for (int j = 0; j < 2; j++) wmma::fill_fragment(acc[i][j], 0.f);

    for (int c = 0; c < chunksTot; ++c) {
        const float* Ap; const __half* Bp; int kloc;
        if (c < chunksA) { Ap = A0; Bp = B0; kloc = c * 64; }
        else             { Ap = A1; Bp = B1; kloc = (c - chunksA) * 64; }

#pragma unroll
        for (int i = tid; i < 2048; i += 256) {
            const int row = i >> 4, j = i & 15;
            const int grow = mbase + row;
            float4 v = make_float4(0.f, 0.f, 0.f, 0.f);
            if (grow < M) v = *(const float4*)&Ap[(size_t)grow * KSTRIDE + kloc + j * 4];
            *(__half2*)&sm.ld.A[row][j * 4]     = __floats2half2_rn(v.x, v.y);
            *(__half2*)&sm.ld.A[row][j * 4 + 2] = __floats2half2_rn(v.z, v.w);
        }
#pragma unroll
        for (int i = tid; i < 512; i += 256) {
            const int row = i >> 3, j = i & 7;
            int4 v = *(const int4*)&Bp[(size_t)(ncol0 + row) * KSTRIDE + kloc + j * 8];
            *(int4*)&sm.ld.B[row][j * 8] = v;
        }
        __syncthreads();

#pragma unroll
        for (int kk = 0; kk < 64; kk += 16) {
            wmma::fragment<wmma::matrix_a, 16, 16, 16, __half, wmma::row_major> a0, a1;
            wmma::fragment<wmma::matrix_b, 16, 16, 16, __half, wmma::col_major> b0, b1;
            wmma::load_matrix_sync(a0, &sm.ld.A[wm][kk], 72);
            wmma::load_matrix_sync(a1, &sm.ld.A[wm + 16][kk], 72);
            wmma::load_matrix_sync(b0, &sm.ld.B[wn][kk], 72);
            wmma::load_matrix_sync(b1, &sm.ld.B[wn + 16][kk], 72);
            wmma::mma_sync(acc[0][0], a0, b0, acc[0][0]);
            wmma::mma_sync(acc[0][1], a0, b1, acc[0][1]);
            wmma::mma_sync(acc[1][0], a1, b0, acc[1][0]);
            wmma::mma_sync(acc[1][1], a1, b1, acc[1][1]);
        }
        __syncthreads();
    }

    wmma::store_matrix_sync(&sm.C[wm][wn],           acc[0][0], 72, wmma::mem_row_major);
    wmma::store_matrix_sync(&sm.C[wm][wn + 16],      acc[0][1], 72, wmma::mem_row_major);
    wmma::store_matrix_sync(&sm.C[wm + 16][wn],      acc[1][0], 72, wmma::mem_row_major);
    wmma::store_matrix_sync(&sm.C[wm + 16][wn + 16], acc[1][1], 72, wmma::mem_row_major);
    __syncthreads();

#pragma unroll
    for (int i = tid; i < 128 * 16; i += 256) {
        const int row = i >> 4, j = i & 15;
        const int grow = mbase + row;
        if (grow < M) {
            const int col = ncol0 + j * 4;
            float4 v = *(const float4*)&sm.C[row][j * 4];
            if (bias) {
                v.x += bias[col + 0]; v.y += bias[col + 1];
                v.z += bias[col + 2]; v.w += bias[col + 3];
            }
            if (EPI == 0) {
                *(float4*)((float*)Cout + (size_t)grow * NT + col) = v;
            } else {
                __half* Cp = (__half*)Cout + (size_t)grow * NT + col;
                *(__half2*)(Cp)     = __floats2half2_rn(v.x, v.y);
                *(__half2*)(Cp + 2) = __floats2half2_rn(v.z, v.w);
            }
        }
    }
}

// ---------------------------------------------------------------------------
// Joint softmax over 32 = concat(aw0[16], aw1[16]) per (n,q,h); in-place.
// ---------------------------------------------------------------------------
__global__ void softmax_kernel(float* __restrict__ aw0, float* __restrict__ aw1,
                               int total)
{
    int t = blockIdx.x * blockDim.x + threadIdx.x;
    if (t >= total) return;
    float4* p0 = (float4*)(aw0 + (size_t)t * 16);
    float4* p1 = (float4*)(aw1 + (size_t)t * 16);
    float v[32];
    float4 r;
#pragma unroll
    for (int i = 0; i < 4; i++) {
        r = p0[i]; v[i*4+0]=r.x; v[i*4+1]=r.y; v[i*4+2]=r.z; v[i*4+3]=r.w;
    }
#pragma unroll
    for (int i = 0; i < 4; i++) {
        r = p1[i]; v[16+i*4+0]=r.x; v[16+i*4+1]=r.y; v[16+i*4+2]=r.z; v[16+i*4+3]=r.w;
    }
    float mx = v[0];
#pragma unroll
    for (int i = 1; i < 32; i++) mx = fmaxf(mx, v[i]);
    float sum = 0.f;
#pragma unroll
    for (int i = 0; i < 32; i++) { v[i] = expf(v[i] - mx); sum += v[i]; }
    float inv = 1.f / sum;
#pragma unroll
    for (int i = 0; i < 32; i++) v[i] *= inv;
#pragma unroll
    for (int i = 0; i < 4; i++)
        p0[i] = make_float4(v[i*4+0], v[i*4+1], v[i*4+2], v[i*4+3]);
#pragma unroll
    for (int i = 0; i < 4; i++)
        p1[i] = make_float4(v[16+i*4+0], v[16+i*4+1], v[16+i*4+2], v[16+i*4+3]);
}

// ---------------------------------------------------------------------------
// Deformable sampling, full-row version.
//   One warp = one (n,q): 8 head-groups of 4 lanes; lane = 8 channels via one
//   16 B gather per corner.  Width-4 shuffles; all metadata selections are
//   compile-time in the fully-unrolled 16-sample loop.  blockIdx.y = iter.
// ---------------------------------------------------------------------------
__global__ __launch_bounds__(256) void sample8_kernel(
    const __half* __restrict__ v0, const __half* __restrict__ v1,
    const float* __restrict__ ref,
    const float* __restrict__ o0, const float* __restrict__ o1,
    const float* __restrict__ a0, const float* __restrict__ a1,
    float* __restrict__ d0, float* __restrict__ d1)
{
    const int iter = blockIdx.y;
    const __half* value = iter ? v1 : v0;
    const float* off    = iter ? o1 : o0;
    const float* attn   = iter ? a1 : a0;
    float* out          = iter ? d1 : d0;

    const int nq = blockIdx.x * 8 + (threadIdx.x >> 5);
    const int lane = threadIdx.x & 31;
    if (nq >= NROWS) return;

    const int n = nq / LQ;
    const int h = lane >> 2;             // 0..7: head
    const int s = lane & 3;              // 0..3 within head group

    // metadata: vector loads, elements addressed by (srcLane, component)
    //   off: 32 floats/head; element e at lane e>>3, comp e&7
    const size_t ob = ((size_t)nq * NHEADS + h) * 32;
    const float4 ofa = *(const float4*)&off[ob + s * 8];
    const float4 ofb = *(const float4*)&off[ob + s * 8 + 4];
    const float ofr[8] = {ofa.x, ofa.y, ofa.z, ofa.w, ofb.x, ofb.y, ofb.z, ofb.w};
    //   attn: 16 floats/head; element e at lane e>>2, comp e&3
    const float4 at4 = *(const float4*)&attn[((size_t)nq * NHEADS + h) * 16 + s * 4];
    const float atr[4] = {at4.x, at4.y, at4.z, at4.w};
    //   ref: 8 floats/row; element e at lane e>>1, comp e&1
    const float2 rf2 = *(const float2*)&ref[(size_t)nq * 8 + s * 2];
    const float rfr[2] = {rf2.x, rf2.y};

    float acc[8];
#pragma unroll
    for (int i = 0; i < 8; i++) acc[i] = 0.f;

#pragma unroll
    for (int l = 0; l < NLEV; l++) {
        const int H = LVL_H[l], W = LVL_W[l], st = LVL_S[l];
        const float fW = (float)W, fH = (float)H;
        const float rx = __shfl_sync(0xFFFFFFFFu, rfr[(l * 2) & 1],     (l * 2) >> 1, 4);
        const float ry = __shfl_sync(0xFFFFFFFFu, rfr[(l * 2 + 1) & 1], (l * 2 + 1) >> 1, 4);
        const __half* vbase =
            value + (((size_t)n * LQ + st) * NHEADS + h) * HDIM + 8 * s;

#pragma unroll
        for (int p = 0; p < NPTS; p++) {
            const int sp = l * 4 + p;
            const int xi = 2 * sp, yi = 2 * sp + 1;
            const float ox = __shfl_sync(0xFFFFFFFFu, ofr[xi & 7], xi >> 3, 4);
            const float oy = __shfl_sync(0xFFFFFFFFu, ofr[yi & 7], yi >> 3, 4);
            const float a  = __shfl_sync(0xFFFFFFFFu, atr[sp & 3], sp >> 2, 4);

            // match reference arithmetic order exactly
            float x = (rx + ox / fW) * fW - 0.5f;
            float y = (ry + oy / fH) * fH - 0.5f;
            float x0f = floorf(x), y0f = floorf(y);
            int x0 = (int)x0f, y0 = (int)y0f;
            float lx = x - x0f, ly = y - y0f;
            float hx = 1.f - lx, hy = 1.f - ly;

            float smp[8];
#pragma unroll
            for (int i = 0; i < 8; i++) smp[i] = 0.f;
            const bool xin0 = (x0 >= 0) & (x0 < W);
            const bool xin1 = (x0 + 1 >= 0) & (x0 + 1 < W);
            const bool yin0 = (y0 >= 0) & (y0 < H);
            const bool yin1 = (y0 + 1 >= 0) & (y0 + 1 < H);
            if (xin0 & yin0) {
                uint4 u = *(const uint4*)(vbase + (size_t)(y0 * W + x0) * DMODEL);
                float w = hy * hx;
                float2 va = __half22float2(*(__half2*)&u.x), vb = __half22float2(*(__half2*)&u.y);
                float2 vc = __half22float2(*(__half2*)&u.z), vd = __half22float2(*(__half2*)&u.w);
                smp[0] = fmaf(w, va.x, smp[0]); smp[1] = fmaf(w, va.y, smp[1]);
                smp[2] = fmaf(w, vb.x, smp[2]); smp[3] = fmaf(w, vb.y, smp[3]);
                smp[4] = fmaf(w, vc.x, smp[4]); smp[5] = fmaf(w, vc.y, smp[5]);
                smp[6] = fmaf(w, vd.x, smp[6]); smp[7] = fmaf(w, vd.y, smp[7]);
            }
            if (xin1 & yin0) {
                uint4 u = *(const uint4*)(vbase + (size_t)(y0 * W + x0 + 1) * DMODEL);
                float w = hy * lx;
                float2 va = __half22float2(*(__half2*)&u.x), vb = __half22float2(*(__half2*)&u.y);
                float2 vc = __half22float2(*(__half2*)&u.z), vd = __half22float2(*(__half2*)&u.w);
                smp[0] = fmaf(w, va.x, smp[0]); smp[1] = fmaf(w, va.y, smp[1]);
                smp[2] = fmaf(w, vb.x, smp[2]); smp[3] = fmaf(w, vb.y, smp[3]);
                smp[4] = fmaf(w, vc.x, smp[4]); smp[5] = fmaf(w, vc.y, smp[5]);
                smp[6] = fmaf(w, vd.x, smp[6]); smp[7] = fmaf(w, vd.y, smp[7]);
            }
            if (xin0 & yin1) {
                uint4 u = *(const uint4*)(vbase + (size_t)((y0 + 1) * W + x0) * DMODEL);
                float w = ly * hx;
                float2 va = __half22float2(*(__half2*)&u.x), vb = __half22float2(*(__half2*)&u.y);
                float2 vc = __half22float2(*(__half2*)&u.z), vd = __half22float2(*(__half2*)&u.w);
                smp[0] = fmaf(w, va.x, smp[0]); smp[1] = fmaf(w, va.y, smp[1]);
                smp[2] = fmaf(w, vb.x, smp[2]); smp[3] = fmaf(w, vb.y, smp[3]);
                smp[4] = fmaf(w, vc.x, smp[4]); smp[5] = fmaf(w, vc.y, smp[5]);
                smp[6] = fmaf(w, vd.x, smp[6]); smp[7] = fmaf(w, vd.y, smp[7]);
            }
            if (xin1 & yin1) {
                uint4 u = *(const uint4*)(vbase + (size_t)((y0 + 1) * W + x0 + 1) * DMODEL);
                float w = ly * lx;
                float2 va = __half22float2(*(__half2*)&u.x), vb = __half22float2(*(__half2*)&u.y);
                float2 vc = __half22float2(*(__half2*)&u.z), vd = __half22float2(*(__half2*)&u.w);
                smp[0] = fmaf(w, va.x, smp[0]); smp[1] = fmaf(w, va.y, smp[1]);
                smp[2] = fmaf(w, vb.x, smp[2]); smp[3] = fmaf(w, vb.y, smp[3]);
                smp[4] = fmaf(w, vc.x, smp[4]); smp[5] = fmaf(w, vc.y, smp[5]);
                smp[6] = fmaf(w, vd.x, smp[6]); smp[7] = fmaf(w, vd.y, smp[7]);
            }
#pragma unroll
            for (int i = 0; i < 8; i++) acc[i] = fmaf(a, smp[i], acc[i]);
        }
    }

    float* op = &out[(size_t)nq * DMODEL + h * HDIM + 8 * s];
    *(float4*)op       = make_float4(acc[0], acc[1], acc[2], acc[3]);
    *(float4*)(op + 4) = make_float4(acc[4], acc[5], acc[6], acc[7]);
}

// ---------------------------------------------------------------------------
// Launcher
// ---------------------------------------------------------------------------
extern "C" void kernel_launch(void* const* d_in, const int* in_sizes, int n_in,
                              void* d_out, int out_size)
{
    const float* q0     = (const float*)d_in[0];
    const float* q1     = (const float*)d_in[1];
    const float* ref    = (const float*)d_in[2];
    const float* flat0  = (const float*)d_in[3];
    const float* flat1  = (const float*)d_in[4];
    const float* W_so   = (const float*)d_in[7];
    const float* b_so   = (const float*)d_in[8];
    const float* W_aw   = (const float*)d_in[9];
    const float* b_aw   = (const float*)d_in[10];
    const float* W_v    = (const float*)d_in[11];
    const float* b_v    = (const float*)d_in[12];
    const float* W_o    = (const float*)d_in[13];
    const float* b_o    = (const float*)d_in[14];
    const float* W_agg  = (const float*)d_in[15];
    const float* b_agg  = (const float*)d_in[16];
    float* out = (float*)d_out;

    __half *value0, *value1, *Whv, *Whso, *Whaw, *Whf0, *Whf1;
    float *off0, *off1, *aw0, *aw1, *dd0, *dd1, *bf;
    cudaGetSymbolAddress((void**)&value0, g_value0);
    cudaGetSymbolAddress((void**)&value1, g_value1);
    cudaGetSymbolAddress((void**)&off0, g_off0);
    cudaGetSymbolAddress((void**)&off1, g_off1);
    cudaGetSymbolAddress((void**)&aw0, g_aw0);
    cudaGetSymbolAddress((void**)&aw1, g_aw1);
    cudaGetSymbolAddress((void**)&dd0, g_d0);
    cudaGetSymbolAddress((void**)&dd1, g_d1);
    cudaGetSymbolAddress((void**)&Whv, g_Whv);
    cudaGetSymbolAddress((void**)&Whso, g_Whso);
    cudaGetSymbolAddress((void**)&Whaw, g_Whaw);
    cudaGetSymbolAddress((void**)&Whf0, g_Whf0);
    cudaGetSymbolAddress((void**)&Whf1, g_Whf1);
    cudaGetSymbolAddress((void**)&bf, g_bf);

    dim3 blk(256);
    const int MT = (NROWS + 127) / 128;   // 306

    // --- fused weight prep: 3 launches ---
    transpose_batch_kernel<<<dim3(8, 8, 3), dim3(32, 8)>>>(W_v, W_so, W_aw,
                                                           Whv, Whso, Whaw);
    wfprep_kernel<<<dim3(16, 2), blk>>>(W_o, W_agg, Whf0, Whf1);
    fuse_bias_kernel<<<1, DMODEL>>>(b_o, b_agg, W_agg, bf);

    // --- big projections ---
    gemm_hmma<256, 1><<<dim3(4, MT), blk>>>(flat0, flat0, 4, Whv, Whv, 4, b_v, value0, NROWS);
    gemm_hmma<256, 1><<<dim3(4, MT), blk>>>(flat1, flat1, 4, Whv, Whv, 4, b_v, value1, NROWS);
    gemm_hmma<256, 0><<<dim3(4, MT), blk>>>(q0, q0, 4, Whso, Whso, 4, b_so, off0, NROWS);
    gemm_hmma<256, 0><<<dim3(4, MT), blk>>>(q1, q1, 4, Whso, Whso, 4, b_so, off1, NROWS);
    gemm_hmma<128, 0><<<dim3(2, MT), blk>>>(q0, q0, 4, Whaw, Whaw, 4, b_aw, aw0, NROWS);
    gemm_hmma<128, 0><<<dim3(2, MT), blk>>>(q1, q1, 4, Whaw, Whaw, 4, b_aw, aw1, NROWS);

    // --- joint softmax over 32 ---
    {
        int total = NROWS * NHEADS;
        softmax_kernel<<<(total + 255) / 256, 256>>>(aw0, aw1, total);
    }

    // --- deformable sampling: one warp per (n,q), both iters in one launch ---
    {
        int blocks = (NROWS + 7) / 8;   // 4890
        sample8_kernel<<<dim3(blocks, 2), blk>>>(value0, value1, ref,
                                                 off0, off1, aw0, aw1, dd0, dd1);
    }

    // --- fused output projection: out = d0@Whf0^T + d1@Whf1^T + bf (K=512) ---
    gemm_hmma<256, 0><<<dim3(4, MT), blk>>>(dd0, dd1, 4, Whf0, Whf1, 8, bf, out, NROWS);

    (void)in_sizes; (void)n_in; (void)out_size;
}